// round 10
// baseline (speedup 1.0000x reference)
#include <cuda_runtime.h>
#include <math.h>
#include <stdint.h>

#define BB 8
#define SS 4096
#define HH 2048
#define EE 8
#define CAP 512
#define NTOK (BB*SS)            /* 32768 */

#define GSPLIT 8
#define KCHUNK 256              /* HH / GSPLIT */

#define K1_BLOCKS 256
#define K1_THREADS 128
#define TOK_PER_BLOCK 128

#define FIN_BLOCKS 128          /* 256 tokens each == half a capacity segment */
#define FIN_THREADS 256

#define DIS_BLOCKS 64           /* 512 tokens each == one capacity segment */

#define D_OFF ((size_t)0)
#define C_OFF ((size_t)NTOK*EE)
#define P_OFF ((size_t)2*NTOK*EE)
#define AUX_OFF ((size_t)3*NTOK*EE)
#define Z_OFF (AUX_OFF+1)

__device__ float g_part[(size_t)GSPLIT * NTOK * 8];   // partial logits per K-chunk
__device__ float g_wt[NTOK];
__device__ int   g_idx[NTOK];
__device__ int   g_segcnt[FIN_BLOCKS * 8];            // per-HALF-segment expert counts
__device__ float g_p2[FIN_BLOCKS];
__device__ float g_z2[FIN_BLOCKS];

// ---- packed f32x2 helpers (Blackwell FFMA2 path) ---------------------------
__device__ __forceinline__ unsigned long long pack2(float x) {
    unsigned long long r; int xi = __float_as_int(x);
    asm("mov.b64 %0, {%1, %1};" : "=l"(r) : "r"(xi));
    return r;
}
__device__ __forceinline__ unsigned long long fma2(unsigned long long a,
    unsigned long long b, unsigned long long c) {
    unsigned long long d;
    asm("fma.rn.f32x2 %0, %1, %2, %3;" : "=l"(d) : "l"(a), "l"(b), "l"(c));
    return d;
}
__device__ __forceinline__ unsigned long long add2(unsigned long long a,
    unsigned long long b) {
    unsigned long long d;
    asm("add.rn.f32x2 %0, %1, %2;" : "=l"(d) : "l"(a), "l"(b));
    return d;
}
__device__ __forceinline__ float2 unpack2(unsigned long long v) {
    int lo, hi;
    asm("mov.b64 {%0, %1}, %2;" : "=r"(lo), "=r"(hi) : "l"(v));
    return make_float2(__int_as_float(lo), __int_as_float(hi));
}

// ---------------------------------------------------------------------------
// Kernel 1: partial router GEMM over one 256-wide K chunk (blockIdx.y).
// Warp: 8 token-groups x 4 lanes; lane s covers h-slices (h16+s*4..+3).
// Accumulators are packed f32x2 expert-pairs -> FFMA2. unroll 4 -> 16 LDG.128
// batched per lane. Hidden read via __ldcs (streaming; no reuse).
// ---------------------------------------------------------------------------
__global__ __launch_bounds__(K1_THREADS, 6) void router_partial_kernel(
    const float* __restrict__ hs, const float* __restrict__ Wr)
{
    __shared__ float sW[(KCHUNK / 4) * 36];   // 64 regions * 36 floats (padded)

    const int tid  = threadIdx.x;
    const int w    = tid >> 5;
    const int lane = tid & 31;
    const int g    = lane >> 2;
    const int s    = lane & 3;
    const int tokBase = blockIdx.x * TOK_PER_BLOCK + w * 32 + g * 4;
    const int hc = blockIdx.y * KCHUNK;

    unsigned long long acc[4][4];   // [token][expert-pair], f32x2 packed
#pragma unroll
    for (int i = 0; i < 4; i++)
#pragma unroll
        for (int p = 0; p < 4; p++) acc[i][p] = 0ull;

    const float4* __restrict__ hs4 = reinterpret_cast<const float4*>(hs);
    const float4* __restrict__ W4  = reinterpret_cast<const float4*>(Wr);

    // stage W[hc..hc+256) into padded smem: 512 float4 loads
#pragma unroll
    for (int q = tid; q < KCHUNK * 2; q += K1_THREADS) {
        int hl = q >> 1, part = q & 1;
        float4 v = W4[(hc + hl) * 2 + part];
        *reinterpret_cast<float4*>(&sW[(hl >> 2) * 36 + (hl & 3) * 8 + part * 4]) = v;
    }
    __syncthreads();

#pragma unroll 4
    for (int h16 = 0; h16 < KCHUNK; h16 += 16) {
        // lane's 4 h-rows of W as 8 pairs-of-pairs (LDS.128)
        const ulonglong2* wp = reinterpret_cast<const ulonglong2*>(&sW[(h16 / 4 + s) * 36]);
        ulonglong2 wv[8];
#pragma unroll
        for (int j = 0; j < 8; j++) wv[j] = wp[j];

        const int hg = hc + h16 + s * 4;
#pragma unroll
        for (int i = 0; i < 4; i++) {
            float4 hv = __ldcs(&hs4[((size_t)(tokBase + i) * HH + hg) >> 2]);
            const float* hvp = &hv.x;
#pragma unroll
            for (int k = 0; k < 4; k++) {
                unsigned long long xx = pack2(hvp[k]);
                acc[i][0] = fma2(xx, wv[2 * k].x,     acc[i][0]);
                acc[i][1] = fma2(xx, wv[2 * k].y,     acc[i][1]);
                acc[i][2] = fma2(xx, wv[2 * k + 1].x, acc[i][2]);
                acc[i][3] = fma2(xx, wv[2 * k + 1].y, acc[i][3]);
            }
        }
    }

    // reduce K-partials across the 4 lanes of each token-group (f32x2 adds)
#pragma unroll
    for (int i = 0; i < 4; i++)
#pragma unroll
        for (int p = 0; p < 4; p++) {
            unsigned long long v = acc[i][p];
            v = add2(v, __shfl_xor_sync(0xffffffffu, v, 1));
            v = add2(v, __shfl_xor_sync(0xffffffffu, v, 2));
            acc[i][p] = v;
        }

    // lane s takes token tokBase+s (static selection), unpack, write 8 floats
    const int tok = tokBase + s;
    unsigned long long sel[4];
#pragma unroll
    for (int p = 0; p < 4; p++) {
        unsigned long long v = acc[0][p];
        if (s == 1) v = acc[1][p];
        if (s == 2) v = acc[2][p];
        if (s == 3) v = acc[3][p];
        sel[p] = v;
    }
    float2 e01 = unpack2(sel[0]), e23 = unpack2(sel[1]);
    float2 e45 = unpack2(sel[2]), e67 = unpack2(sel[3]);
    float4* po = reinterpret_cast<float4*>(&g_part[((size_t)blockIdx.y * NTOK + tok) * 8]);
    po[0] = make_float4(e01.x, e01.y, e23.x, e23.y);
    po[1] = make_float4(e45.x, e45.y, e67.x, e67.y);
}

// ---------------------------------------------------------------------------
// Kernel 2: finalize — sum partials, softmax, argmax, probs, half-segment
// expert counts, per-block loss partials. One block == 256 tokens.
// ---------------------------------------------------------------------------
__global__ __launch_bounds__(FIN_THREADS) void finalize_kernel(float* __restrict__ out)
{
    __shared__ float sRedP[8];
    __shared__ float sRedZ[8];
    __shared__ int   sCnt[8];
    const int tid = threadIdx.x;
    const int tok = blockIdx.x * FIN_THREADS + tid;

    if (tid < 8) sCnt[tid] = 0;
    __syncthreads();

    const float4* p4 = reinterpret_cast<const float4*>(g_part);
    float4 a = p4[(size_t)tok * 2];
    float4 b = p4[(size_t)tok * 2 + 1];
#pragma unroll
    for (int y = 1; y < GSPLIT; y++) {
        float4 pa = p4[((size_t)y * NTOK + tok) * 2];
        float4 pb = p4[((size_t)y * NTOK + tok) * 2 + 1];
        a.x += pa.x; a.y += pa.y; a.z += pa.z; a.w += pa.w;
        b.x += pb.x; b.y += pb.y; b.z += pb.z; b.w += pb.w;
    }
    float l[8] = {a.x, a.y, a.z, a.w, b.x, b.y, b.z, b.w};

    float m = l[0]; int bi = 0;
#pragma unroll
    for (int e = 1; e < 8; e++) { if (l[e] > m) { m = l[e]; bi = e; } }

    float pe[8], sum = 0.0f;
#pragma unroll
    for (int e = 0; e < 8; e++) { pe[e] = expf(l[e] - m); sum += pe[e]; }
    float inv = 1.0f / sum;
    float p2 = 0.0f, wmax = 0.0f;
#pragma unroll
    for (int e = 0; e < 8; e++) { pe[e] *= inv; p2 += pe[e] * pe[e]; if (e == bi) wmax = pe[e]; }
    float lse = m + logf(sum);
    float z2 = lse * lse;

    float4* po = reinterpret_cast<float4*>(out + P_OFF + (size_t)tok * 8);
    po[0] = make_float4(pe[0], pe[1], pe[2], pe[3]);
    po[1] = make_float4(pe[4], pe[5], pe[6], pe[7]);
    g_idx[tok] = bi;
    g_wt[tok]  = wmax;
    atomicAdd(&sCnt[bi], 1);   // counts: order-independent -> deterministic

    const int w = tid >> 5, lane = tid & 31;
#pragma unroll
    for (int off = 16; off > 0; off >>= 1) {
        p2 += __shfl_down_sync(0xffffffffu, p2, off);
        z2 += __shfl_down_sync(0xffffffffu, z2, off);
    }
    if (lane == 0) { sRedP[w] = p2; sRedZ[w] = z2; }
    __syncthreads();
    if (tid == 0) {
        float tp = 0.0f, tz = 0.0f;
#pragma unroll
        for (int i = 0; i < 8; i++) { tp += sRedP[i]; tz += sRedZ[i]; }
        g_p2[blockIdx.x] = tp;
        g_z2[blockIdx.x] = tz;
    }
    if (tid < 8) g_segcnt[blockIdx.x * 8 + tid] = sCnt[tid];
}

// ---------------------------------------------------------------------------
// Kernel 3: dispatch/combine + loss. One block per 512-token segment,
// 1 token/thread. Position = same-row prior HALF-segment counts + in-segment
// exclusive prefix (packed 16-bit fields, warp shuffle scan).
// Block 0 warp 0 also reduces the 128 loss partials.
// ---------------------------------------------------------------------------
__global__ __launch_bounds__(512) void dispatch_kernel(float* __restrict__ out)
{
    __shared__ unsigned long long sW0[16], sW1[16];
    __shared__ int sBase[8];
    const int blk = blockIdx.x;
    const int b = blk >> 3, seg = blk & 7;
    const int t = threadIdx.x;
    const int w = t >> 5, lane = t & 31;
    const int tok = blk * 512 + t;

    // loss reduction folded in (block 0, warp 0)
    if (blk == 0 && w == 0) {
        float lp = g_p2[lane] + g_p2[lane + 32] + g_p2[lane + 64] + g_p2[lane + 96];
        float lz = g_z2[lane] + g_z2[lane + 32] + g_z2[lane + 64] + g_z2[lane + 96];
#pragma unroll
        for (int off = 16; off > 0; off >>= 1) {
            lp += __shfl_down_sync(0xffffffffu, lp, off);
            lz += __shfl_down_sync(0xffffffffu, lz, off);
        }
        if (lane == 0) {
            out[AUX_OFF] = (lp / (float)NTOK) * (float)EE;
            out[Z_OFF]   = lz / (float)NTOK;
        }
    }

    // prior half-segment counts in this batch row (halves [b*16, b*16+seg*2))
    if (t < 8) {
        int sbase = 0;
#pragma unroll
        for (int q = 0; q < 14; q++)
            if (q < 2 * seg) sbase += g_segcnt[((b << 4) + q) * 8 + t];
        sBase[t] = sbase;
    }

    const int e = g_idx[tok];
    const float wt = g_wt[tok];
    const int sh = (e & 3) * 16;
    unsigned long long c0 = (e < 4)  ? (1ull << sh) : 0ull;
    unsigned long long c1 = (e >= 4) ? (1ull << sh) : 0ull;

    unsigned long long i0 = c0, i1 = c1;     // inclusive warp scan
#pragma unroll
    for (int off = 1; off < 32; off <<= 1) {
        unsigned long long v0 = __shfl_up_sync(0xffffffffu, i0, off);
        unsigned long long v1 = __shfl_up_sync(0xffffffffu, i1, off);
        if (lane >= off) { i0 += v0; i1 += v1; }
    }
    if (lane == 31) { sW0[w] = i0; sW1[w] = i1; }
    __syncthreads();
    unsigned long long wp0 = 0ull, wp1 = 0ull;
#pragma unroll
    for (int i = 0; i < 15; i++)
        if (i < w) { wp0 += sW0[i]; wp1 += sW1[i]; }
    unsigned long long r0 = wp0 + i0 - c0;   // exclusive per-token prefix
    unsigned long long r1 = wp1 + i1 - c1;

    const int pos = sBase[e] + (int)((((e < 4) ? r0 : r1) >> sh) & 0xffffull);
    const float dv = (pos < CAP) ? 1.0f : 0.0f;

    float d[8];
#pragma unroll
    for (int q = 0; q < 8; q++) d[q] = (e == q) ? dv : 0.0f;

    const size_t o = (size_t)tok * 8;
    float4* dp = reinterpret_cast<float4*>(out + D_OFF + o);
    dp[0] = make_float4(d[0], d[1], d[2], d[3]);
    dp[1] = make_float4(d[4], d[5], d[6], d[7]);
    float4* cp = reinterpret_cast<float4*>(out + C_OFF + o);
    cp[0] = make_float4(d[0] * wt, d[1] * wt, d[2] * wt, d[3] * wt);
    cp[1] = make_float4(d[4] * wt, d[5] * wt, d[6] * wt, d[7] * wt);
}

// ---------------------------------------------------------------------------
extern "C" void kernel_launch(void* const* d_in, const int* in_sizes, int n_in,
                              void* d_out, int out_size)
{
    const float* hs = (const float*)d_in[0];
    const float* Wr = (const float*)d_in[1];
    if (n_in >= 2 && in_sizes[0] == HH * EE && in_sizes[1] == NTOK * HH) {
        hs = (const float*)d_in[1];
        Wr = (const float*)d_in[0];
    }
    float* out = (float*)d_out;

    router_partial_kernel<<<dim3(K1_BLOCKS, GSPLIT), K1_THREADS>>>(hs, Wr);
    finalize_kernel<<<FIN_BLOCKS, FIN_THREADS>>>(out);
    dispatch_kernel<<<DIS_BLOCKS, 512>>>(out);
}

// round 11
// speedup vs baseline: 1.0669x; 1.0669x over previous
#include <cuda_runtime.h>
#include <math.h>
#include <stdint.h>

#define BB 8
#define SS 4096
#define HH 2048
#define EE 8
#define CAP 512
#define NTOK (BB*SS)            /* 32768 */

#define GSPLIT 8
#define KCHUNK 256              /* HH / GSPLIT */

#define K1_BLOCKS 256
#define K1_THREADS 128
#define TOK_PER_BLOCK 128

#define FIN_BLOCKS 128          /* 256 tokens each == half a capacity segment */
#define FIN_THREADS 256

#define DIS_BLOCKS 64           /* 512 tokens each == one capacity segment */

#define D_OFF ((size_t)0)
#define C_OFF ((size_t)NTOK*EE)
#define P_OFF ((size_t)2*NTOK*EE)
#define AUX_OFF ((size_t)3*NTOK*EE)
#define Z_OFF (AUX_OFF+1)

__device__ float g_part[(size_t)GSPLIT * NTOK * 8];   // partial logits per K-chunk
__device__ float g_wt[NTOK];
__device__ int   g_idx[NTOK];
__device__ int   g_segcnt[FIN_BLOCKS * 8];            // per-HALF-segment expert counts
__device__ float g_p2[FIN_BLOCKS];
__device__ float g_z2[FIN_BLOCKS];

// ---- packed f32x2 helpers (Blackwell FFMA2 path) ---------------------------
__device__ __forceinline__ unsigned long long pack2(float x) {
    unsigned long long r; int xi = __float_as_int(x);
    asm("mov.b64 %0, {%1, %1};" : "=l"(r) : "r"(xi));
    return r;
}
__device__ __forceinline__ unsigned long long fma2(unsigned long long a,
    unsigned long long b, unsigned long long c) {
    unsigned long long d;
    asm("fma.rn.f32x2 %0, %1, %2, %3;" : "=l"(d) : "l"(a), "l"(b), "l"(c));
    return d;
}
__device__ __forceinline__ unsigned long long add2(unsigned long long a,
    unsigned long long b) {
    unsigned long long d;
    asm("add.rn.f32x2 %0, %1, %2;" : "=l"(d) : "l"(a), "l"(b));
    return d;
}
__device__ __forceinline__ float2 unpack2(unsigned long long v) {
    int lo, hi;
    asm("mov.b64 {%0, %1}, %2;" : "=r"(lo), "=r"(hi) : "l"(v));
    return make_float2(__int_as_float(lo), __int_as_float(hi));
}

// ---------------------------------------------------------------------------
// Kernel 1: partial router GEMM over one 256-wide K chunk (blockIdx.y).
// Warp: 8 token-groups x 4 lanes; lane s covers h-slices (h16+s*4..+3).
// Accumulators are packed f32x2 expert-pairs -> FFMA2. unroll 4 -> 16 LDG.128
// batched per lane. EXACT R8 configuration (measured 53.2us @ DRAM 63.7%):
// launch_bounds(128,5), plain loads, 96 regs — regs are the load buffers.
// ---------------------------------------------------------------------------
__global__ __launch_bounds__(K1_THREADS, 5) void router_partial_kernel(
    const float* __restrict__ hs, const float* __restrict__ Wr)
{
    __shared__ float sW[(KCHUNK / 4) * 36];   // 64 regions * 36 floats (padded)

    const int tid  = threadIdx.x;
    const int w    = tid >> 5;
    const int lane = tid & 31;
    const int g    = lane >> 2;
    const int s    = lane & 3;
    const int tokBase = blockIdx.x * TOK_PER_BLOCK + w * 32 + g * 4;
    const int hc = blockIdx.y * KCHUNK;

    unsigned long long acc[4][4];   // [token][expert-pair], f32x2 packed
#pragma unroll
    for (int i = 0; i < 4; i++)
#pragma unroll
        for (int p = 0; p < 4; p++) acc[i][p] = 0ull;

    const float4* __restrict__ hs4 = reinterpret_cast<const float4*>(hs);
    const float4* __restrict__ W4  = reinterpret_cast<const float4*>(Wr);

    // stage W[hc..hc+256) into padded smem: 512 float4 loads
#pragma unroll
    for (int q = tid; q < KCHUNK * 2; q += K1_THREADS) {
        int hl = q >> 1, part = q & 1;
        float4 v = W4[(hc + hl) * 2 + part];
        *reinterpret_cast<float4*>(&sW[(hl >> 2) * 36 + (hl & 3) * 8 + part * 4]) = v;
    }
    __syncthreads();

#pragma unroll 4
    for (int h16 = 0; h16 < KCHUNK; h16 += 16) {
        // lane's 4 h-rows of W as 8 pairs-of-pairs (LDS.128)
        const ulonglong2* wp = reinterpret_cast<const ulonglong2*>(&sW[(h16 / 4 + s) * 36]);
        ulonglong2 wv[8];
#pragma unroll
        for (int j = 0; j < 8; j++) wv[j] = wp[j];

        const int hg = hc + h16 + s * 4;
#pragma unroll
        for (int i = 0; i < 4; i++) {
            float4 hv = hs4[((size_t)(tokBase + i) * HH + hg) >> 2];
            const float* hvp = &hv.x;
#pragma unroll
            for (int k = 0; k < 4; k++) {
                unsigned long long xx = pack2(hvp[k]);
                acc[i][0] = fma2(xx, wv[2 * k].x,     acc[i][0]);
                acc[i][1] = fma2(xx, wv[2 * k].y,     acc[i][1]);
                acc[i][2] = fma2(xx, wv[2 * k + 1].x, acc[i][2]);
                acc[i][3] = fma2(xx, wv[2 * k + 1].y, acc[i][3]);
            }
        }
    }

    // reduce K-partials across the 4 lanes of each token-group (f32x2 adds)
#pragma unroll
    for (int i = 0; i < 4; i++)
#pragma unroll
        for (int p = 0; p < 4; p++) {
            unsigned long long v = acc[i][p];
            v = add2(v, __shfl_xor_sync(0xffffffffu, v, 1));
            v = add2(v, __shfl_xor_sync(0xffffffffu, v, 2));
            acc[i][p] = v;
        }

    // lane s takes token tokBase+s (static selection), unpack, write 8 floats
    const int tok = tokBase + s;
    unsigned long long sel[4];
#pragma unroll
    for (int p = 0; p < 4; p++) {
        unsigned long long v = acc[0][p];
        if (s == 1) v = acc[1][p];
        if (s == 2) v = acc[2][p];
        if (s == 3) v = acc[3][p];
        sel[p] = v;
    }
    float2 e01 = unpack2(sel[0]), e23 = unpack2(sel[1]);
    float2 e45 = unpack2(sel[2]), e67 = unpack2(sel[3]);
    float4* po = reinterpret_cast<float4*>(&g_part[((size_t)blockIdx.y * NTOK + tok) * 8]);
    po[0] = make_float4(e01.x, e01.y, e23.x, e23.y);
    po[1] = make_float4(e45.x, e45.y, e67.x, e67.y);
}

// ---------------------------------------------------------------------------
// Kernel 2: finalize — sum partials, softmax, argmax, probs, half-segment
// expert counts, per-block loss partials. One block == 256 tokens.
// ---------------------------------------------------------------------------
__global__ __launch_bounds__(FIN_THREADS) void finalize_kernel(float* __restrict__ out)
{
    __shared__ float sRedP[8];
    __shared__ float sRedZ[8];
    __shared__ int   sCnt[8];
    const int tid = threadIdx.x;
    const int tok = blockIdx.x * FIN_THREADS + tid;

    if (tid < 8) sCnt[tid] = 0;
    __syncthreads();

    const float4* p4 = reinterpret_cast<const float4*>(g_part);
    float4 a = p4[(size_t)tok * 2];
    float4 b = p4[(size_t)tok * 2 + 1];
#pragma unroll
    for (int y = 1; y < GSPLIT; y++) {
        float4 pa = p4[((size_t)y * NTOK + tok) * 2];
        float4 pb = p4[((size_t)y * NTOK + tok) * 2 + 1];
        a.x += pa.x; a.y += pa.y; a.z += pa.z; a.w += pa.w;
        b.x += pb.x; b.y += pb.y; b.z += pb.z; b.w += pb.w;
    }
    float l[8] = {a.x, a.y, a.z, a.w, b.x, b.y, b.z, b.w};

    float m = l[0]; int bi = 0;
#pragma unroll
    for (int e = 1; e < 8; e++) { if (l[e] > m) { m = l[e]; bi = e; } }

    float pe[8], sum = 0.0f;
#pragma unroll
    for (int e = 0; e < 8; e++) { pe[e] = expf(l[e] - m); sum += pe[e]; }
    float inv = 1.0f / sum;
    float p2 = 0.0f, wmax = 0.0f;
#pragma unroll
    for (int e = 0; e < 8; e++) { pe[e] *= inv; p2 += pe[e] * pe[e]; if (e == bi) wmax = pe[e]; }
    float lse = m + logf(sum);
    float z2 = lse * lse;

    float4* po = reinterpret_cast<float4*>(out + P_OFF + (size_t)tok * 8);
    po[0] = make_float4(pe[0], pe[1], pe[2], pe[3]);
    po[1] = make_float4(pe[4], pe[5], pe[6], pe[7]);
    g_idx[tok] = bi;
    g_wt[tok]  = wmax;
    atomicAdd(&sCnt[bi], 1);   // counts: order-independent -> deterministic

    const int w = tid >> 5, lane = tid & 31;
#pragma unroll
    for (int off = 16; off > 0; off >>= 1) {
        p2 += __shfl_down_sync(0xffffffffu, p2, off);
        z2 += __shfl_down_sync(0xffffffffu, z2, off);
    }
    if (lane == 0) { sRedP[w] = p2; sRedZ[w] = z2; }
    __syncthreads();
    if (tid == 0) {
        float tp = 0.0f, tz = 0.0f;
#pragma unroll
        for (int i = 0; i < 8; i++) { tp += sRedP[i]; tz += sRedZ[i]; }
        g_p2[blockIdx.x] = tp;
        g_z2[blockIdx.x] = tz;
    }
    if (tid < 8) g_segcnt[blockIdx.x * 8 + tid] = sCnt[tid];
}

// ---------------------------------------------------------------------------
// Kernel 3: dispatch/combine + loss. One block per 512-token segment,
// 1 token/thread. Position = same-row prior HALF-segment counts + in-segment
// exclusive prefix (packed 16-bit fields, warp shuffle scan).
// Block 0 warp 0 also reduces the 128 loss partials.
// ---------------------------------------------------------------------------
__global__ __launch_bounds__(512) void dispatch_kernel(float* __restrict__ out)
{
    __shared__ unsigned long long sW0[16], sW1[16];
    __shared__ int sBase[8];
    const int blk = blockIdx.x;
    const int b = blk >> 3, seg = blk & 7;
    const int t = threadIdx.x;
    const int w = t >> 5, lane = t & 31;
    const int tok = blk * 512 + t;

    // loss reduction folded in (block 0, warp 0)
    if (blk == 0 && w == 0) {
        float lp = g_p2[lane] + g_p2[lane + 32] + g_p2[lane + 64] + g_p2[lane + 96];
        float lz = g_z2[lane] + g_z2[lane + 32] + g_z2[lane + 64] + g_z2[lane + 96];
#pragma unroll
        for (int off = 16; off > 0; off >>= 1) {
            lp += __shfl_down_sync(0xffffffffu, lp, off);
            lz += __shfl_down_sync(0xffffffffu, lz, off);
        }
        if (lane == 0) {
            out[AUX_OFF] = (lp / (float)NTOK) * (float)EE;
            out[Z_OFF]   = lz / (float)NTOK;
        }
    }

    // prior half-segment counts in this batch row (halves [b*16, b*16+seg*2))
    if (t < 8) {
        int sbase = 0;
#pragma unroll
        for (int q = 0; q < 14; q++)
            if (q < 2 * seg) sbase += g_segcnt[((b << 4) + q) * 8 + t];
        sBase[t] = sbase;
    }

    const int e = g_idx[tok];
    const float wt = g_wt[tok];
    const int sh = (e & 3) * 16;
    unsigned long long c0 = (e < 4)  ? (1ull << sh) : 0ull;
    unsigned long long c1 = (e >= 4) ? (1ull << sh) : 0ull;

    unsigned long long i0 = c0, i1 = c1;     // inclusive warp scan
#pragma unroll
    for (int off = 1; off < 32; off <<= 1) {
        unsigned long long v0 = __shfl_up_sync(0xffffffffu, i0, off);
        unsigned long long v1 = __shfl_up_sync(0xffffffffu, i1, off);
        if (lane >= off) { i0 += v0; i1 += v1; }
    }
    if (lane == 31) { sW0[w] = i0; sW1[w] = i1; }
    __syncthreads();
    unsigned long long wp0 = 0ull, wp1 = 0ull;
#pragma unroll
    for (int i = 0; i < 15; i++)
        if (i < w) { wp0 += sW0[i]; wp1 += sW1[i]; }
    unsigned long long r0 = wp0 + i0 - c0;   // exclusive per-token prefix
    unsigned long long r1 = wp1 + i1 - c1;

    const int pos = sBase[e] + (int)((((e < 4) ? r0 : r1) >> sh) & 0xffffull);
    const float dv = (pos < CAP) ? 1.0f : 0.0f;

    float d[8];
#pragma unroll
    for (int q = 0; q < 8; q++) d[q] = (e == q) ? dv : 0.0f;

    const size_t o = (size_t)tok * 8;
    float4* dp = reinterpret_cast<float4*>(out + D_OFF + o);
    dp[0] = make_float4(d[0], d[1], d[2], d[3]);
    dp[1] = make_float4(d[4], d[5], d[6], d[7]);
    float4* cp = reinterpret_cast<float4*>(out + C_OFF + o);
    cp[0] = make_float4(d[0] * wt, d[1] * wt, d[2] * wt, d[3] * wt);
    cp[1] = make_float4(d[4] * wt, d[5] * wt, d[6] * wt, d[7] * wt);
}

// ---------------------------------------------------------------------------
extern "C" void kernel_launch(void* const* d_in, const int* in_sizes, int n_in,
                              void* d_out, int out_size)
{
    const float* hs = (const float*)d_in[0];
    const float* Wr = (const float*)d_in[1];
    if (n_in >= 2 && in_sizes[0] == HH * EE && in_sizes[1] == NTOK * HH) {
        hs = (const float*)d_in[1];
        Wr = (const float*)d_in[0];
    }
    float* out = (float*)d_out;

    router_partial_kernel<<<dim3(K1_BLOCKS, GSPLIT), K1_THREADS>>>(hs, Wr);
    finalize_kernel<<<FIN_BLOCKS, FIN_THREADS>>>(out);
    dispatch_kernel<<<DIS_BLOCKS, 512>>>(out);
}